// round 1
// baseline (speedup 1.0000x reference)
#include <cuda_runtime.h>

#define NN 100000
#define EE 3200000
#define HH 64
#define NGNB 50000

// Scratch (static device memory — no allocation in kernel_launch)
__device__ float g_bufA[NN * HH];
__device__ float g_bufB[NN * HH];
__device__ float g_dinv[NN];
__device__ float g_norm[EE];

__global__ void k_init_deg(float* deg) {
    int i = blockIdx.x * blockDim.x + threadIdx.x;
    if (i < NN) deg[i] = 1.0f;  // self-loop weight
}

__global__ void k_acc_deg(const int* __restrict__ dst, const float* __restrict__ w,
                          float* __restrict__ deg) {
    int e = blockIdx.x * blockDim.x + threadIdx.x;
    if (e < EE) atomicAdd(&deg[dst[e]], w[e]);
}

__global__ void k_dinv(float* d) {
    int i = blockIdx.x * blockDim.x + threadIdx.x;
    if (i < NN) {
        float v = d[i];
        d[i] = (v > 0.0f) ? rsqrtf(v) : 0.0f;
    }
}

__global__ void k_norm(const int* __restrict__ src, const int* __restrict__ dst,
                       const float* __restrict__ w, const float* __restrict__ dinv,
                       float* __restrict__ norm) {
    int e = blockIdx.x * blockDim.x + threadIdx.x;
    if (e < EE) norm[e] = dinv[src[e]] * w[e] * dinv[dst[e]];
}

// agg[i,:] = x[i,:] * dinv[i]^2   (self-loop term; also serves as the zero-init)
__global__ void k_selfinit(const float* __restrict__ x, const float* __restrict__ dinv,
                           float* __restrict__ agg, int F) {
    int idx = blockIdx.x * blockDim.x + threadIdx.x;
    if (idx < NN * F) {
        int i = idx / F;
        float dv = dinv[i];
        agg[idx] = x[idx] * dv * dv;
    }
}

// 6-feature edge aggregation: 8 threads per edge (6 active)
__global__ void k_agg6(const float* __restrict__ x, const int* __restrict__ src,
                       const int* __restrict__ dst, const float* __restrict__ norm,
                       float* __restrict__ agg) {
    int idx = blockIdx.x * blockDim.x + threadIdx.x;
    int e = idx >> 3, f = idx & 7;
    if (e < EE && f < 6) {
        float c = norm[e];
        atomicAdd(&agg[dst[e] * 6 + f], x[src[e] * 6 + f] * c);
    }
}

// 64-feature edge aggregation: one warp per edge, 2 features per lane
__global__ void k_agg64(const float* __restrict__ x, const int* __restrict__ src,
                        const int* __restrict__ dst, const float* __restrict__ norm,
                        float* __restrict__ agg) {
    int gid = blockIdx.x * blockDim.x + threadIdx.x;
    int e = gid >> 5, lane = gid & 31;
    if (e < EE) {
        int s = src[e], d = dst[e];
        float c = norm[e];
        float v0 = x[s * 64 + lane] * c;
        float v1 = x[s * 64 + 32 + lane] * c;
        atomicAdd(&agg[d * 64 + lane], v0);
        atomicAdd(&agg[d * 64 + 32 + lane], v1);
    }
}

// out[row,:] = sigmoid(in[row,:] @ W[K,64] + b)   — in-place safe (rows staged in smem)
template <int K>
__global__ void k_xform(const float* __restrict__ in, const float* __restrict__ W,
                        const float* __restrict__ b, float* __restrict__ out) {
    __shared__ float sW[64 * 64];
    __shared__ float sx[8][64];
    int tid = threadIdx.x;  // 512
    for (int i = tid; i < K * 64; i += 512) sW[i] = W[i];
    int r = tid >> 6, o = tid & 63;
    int row = blockIdx.x * 8 + r;
    if (row < NN && o < K) sx[r][o] = in[row * K + o];
    __syncthreads();
    if (row < NN) {
        float acc = b[o];
#pragma unroll
        for (int k = 0; k < K; k++) acc += sx[r][k] * sW[k * 64 + o];
        out[row * 64 + o] = 1.0f / (1.0f + __expf(-acc));
    }
}

// head: out[row, 0..4] = in[row,:] @ Wl[64,5] + bl   for row < NGNB
__global__ void k_head(const float* __restrict__ in, const float* __restrict__ Wl,
                       const float* __restrict__ bl, float* __restrict__ out) {
    int idx = blockIdx.x * blockDim.x + threadIdx.x;
    int row = idx >> 3, o = idx & 7;
    if (row < NGNB && o < 5) {
        float acc = bl[o];
#pragma unroll
        for (int k = 0; k < 64; k++) acc += in[row * 64 + k] * Wl[k * 5 + o];
        out[row * 5 + o] = acc;
    }
}

extern "C" void kernel_launch(void* const* d_in, const int* in_sizes, int n_in,
                              void* d_out, int out_size) {
    const float* vf  = (const float*)d_in[0];
    const int*   edg = (const int*)d_in[1];
    const float* w   = (const float*)d_in[2];
    const float* W1  = (const float*)d_in[3];
    const float* b1  = (const float*)d_in[4];
    const float* W2  = (const float*)d_in[5];
    const float* b2  = (const float*)d_in[6];
    const float* W3  = (const float*)d_in[7];
    const float* b3  = (const float*)d_in[8];
    const float* W4  = (const float*)d_in[9];
    const float* b4  = (const float*)d_in[10];
    const float* Wl  = (const float*)d_in[11];
    const float* bl  = (const float*)d_in[12];
    float* out = (float*)d_out;

    const int* src = edg;
    const int* dst = edg + EE;

    float *bufA, *bufB, *dinv, *norm;
    cudaGetSymbolAddress((void**)&bufA, g_bufA);
    cudaGetSymbolAddress((void**)&bufB, g_bufB);
    cudaGetSymbolAddress((void**)&dinv, g_dinv);
    cudaGetSymbolAddress((void**)&norm, g_norm);

    const int T = 256;
    // --- graph normalization (once, reused by all 4 layers) ---
    k_init_deg<<<(NN + T - 1) / T, T>>>(dinv);
    k_acc_deg<<<(EE + T - 1) / T, T>>>(dst, w, dinv);
    k_dinv<<<(NN + T - 1) / T, T>>>(dinv);
    k_norm<<<(EE + T - 1) / T, T>>>(src, dst, w, dinv, norm);

    int gridE32 = (EE * 32 + T - 1) / T;   // warp per edge
    int gridE8  = (EE * 8 + T - 1) / T;    // 8 threads per edge
    int gridX   = (NN + 7) / 8;

    // Layer 1: agg(vf, F=6) -> bufA[:,0:6]; xform K=6 -> bufB
    k_selfinit<<<(NN * 6 + T - 1) / T, T>>>(vf, dinv, bufA, 6);
    k_agg6<<<gridE8, T>>>(vf, src, dst, norm, bufA);
    k_xform<6><<<gridX, 512>>>(bufA, W1, b1, bufB);

    // Layer 2: agg(bufB) -> bufA; xform in-place style bufA -> bufA
    k_selfinit<<<(NN * 64 + T - 1) / T, T>>>(bufB, dinv, bufA, 64);
    k_agg64<<<gridE32, T>>>(bufB, src, dst, norm, bufA);
    k_xform<64><<<gridX, 512>>>(bufA, W2, b2, bufA);

    // Layer 3: agg(bufA) -> bufB; xform bufB -> bufB
    k_selfinit<<<(NN * 64 + T - 1) / T, T>>>(bufA, dinv, bufB, 64);
    k_agg64<<<gridE32, T>>>(bufA, src, dst, norm, bufB);
    k_xform<64><<<gridX, 512>>>(bufB, W3, b3, bufB);

    // Layer 4: agg(bufB) -> bufA; xform bufA -> bufA
    k_selfinit<<<(NN * 64 + T - 1) / T, T>>>(bufB, dinv, bufA, 64);
    k_agg64<<<gridE32, T>>>(bufB, src, dst, norm, bufA);
    k_xform<64><<<gridX, 512>>>(bufA, W4, b4, bufA);

    // Head
    k_head<<<(NGNB * 8 + T - 1) / T, T>>>(bufA, Wl, bl, out);
}

// round 2
// speedup vs baseline: 1.7047x; 1.7047x over previous
#include <cuda_runtime.h>

#define NN 100000
#define EE 3200000
#define HH 64
#define NGNB 50000
#define SCAN_T 1024
#define CHUNK ((NN + SCAN_T - 1) / SCAN_T)

// Static device scratch (no allocation in kernel_launch)
__device__ float g_bufA[NN * HH];
__device__ float g_bufB[NN * HH];
__device__ float g_dinv[NN];
__device__ int   g_cnt[NN];
__device__ int   g_rowptr[NN + 1];
__device__ int   g_cursor[NN];
__device__ int   g_csrc[EE];
__device__ float g_cnorm[EE];

// zero counters, init weighted degree with self-loop weight 1.0
__global__ void k_init(float* wdeg, int* cnt) {
    int i = blockIdx.x * blockDim.x + threadIdx.x;
    if (i < NN) { wdeg[i] = 1.0f; cnt[i] = 0; }
}

// histogram: weighted in-degree (for dinv) + edge counts (for CSR)
__global__ void k_hist(const int* __restrict__ dst, const float* __restrict__ w,
                       float* __restrict__ wdeg, int* __restrict__ cnt) {
    int e = blockIdx.x * blockDim.x + threadIdx.x;
    if (e < EE) {
        int d = dst[e];
        atomicAdd(&wdeg[d], w[e]);
        atomicAdd(&cnt[d], 1);
    }
}

__global__ void k_dinv(float* d) {
    int i = blockIdx.x * blockDim.x + threadIdx.x;
    if (i < NN) {
        float v = d[i];
        d[i] = (v > 0.0f) ? rsqrtf(v) : 0.0f;
    }
}

// single-block exclusive scan of cnt -> rowptr (+ cursor copy)
__global__ void k_scan(const int* __restrict__ cnt, int* __restrict__ rowptr,
                       int* __restrict__ cursor) {
    __shared__ int ssum[SCAN_T];
    int tid = threadIdx.x;
    int beg = tid * CHUNK;
    int end = min(beg + CHUNK, NN);
    int s = 0;
    for (int i = beg; i < end; i++) s += cnt[i];
    ssum[tid] = s;
    __syncthreads();
    // Hillis-Steele inclusive scan
    for (int off = 1; off < SCAN_T; off <<= 1) {
        int v = (tid >= off) ? ssum[tid - off] : 0;
        __syncthreads();
        ssum[tid] += v;
        __syncthreads();
    }
    int run = (tid > 0) ? ssum[tid - 1] : 0;
    for (int i = beg; i < end; i++) {
        rowptr[i] = run;
        cursor[i] = run;
        run += cnt[i];
    }
    if (tid == SCAN_T - 1) rowptr[NN] = ssum[SCAN_T - 1];
}

// scatter edges into CSR (by dst), computing norm on the fly
__global__ void k_scatter(const int* __restrict__ src, const int* __restrict__ dst,
                          const float* __restrict__ w, const float* __restrict__ dinv,
                          int* __restrict__ cursor, int* __restrict__ csrc,
                          float* __restrict__ cnorm) {
    int e = blockIdx.x * blockDim.x + threadIdx.x;
    if (e < EE) {
        int s = src[e], d = dst[e];
        int pos = atomicAdd(&cursor[d], 1);
        csrc[pos] = s;
        cnorm[pos] = dinv[s] * w[e] * dinv[d];
    }
}

// pull aggregation, 64 features: one warp per node, atomic-free
__global__ void k_pull64(const float* __restrict__ x, const int* __restrict__ csrc,
                         const float* __restrict__ cnorm, const int* __restrict__ rowptr,
                         const float* __restrict__ dinv, float* __restrict__ out) {
    int gid = blockIdx.x * blockDim.x + threadIdx.x;
    int node = gid >> 5, lane = gid & 31;
    if (node >= NN) return;
    float dv = dinv[node];
    float cs = dv * dv;  // self-loop norm
    float a0 = x[node * 64 + lane] * cs;
    float a1 = x[node * 64 + 32 + lane] * cs;
    int beg = rowptr[node], end = rowptr[node + 1];
    int j = beg;
    for (; j + 1 < end; j += 2) {
        int s0 = csrc[j], s1 = csrc[j + 1];
        float c0 = cnorm[j], c1 = cnorm[j + 1];
        float x00 = x[s0 * 64 + lane],      x01 = x[s0 * 64 + 32 + lane];
        float x10 = x[s1 * 64 + lane],      x11 = x[s1 * 64 + 32 + lane];
        a0 += x00 * c0; a1 += x01 * c0;
        a0 += x10 * c1; a1 += x11 * c1;
    }
    if (j < end) {
        int s0 = csrc[j];
        float c0 = cnorm[j];
        a0 += x[s0 * 64 + lane] * c0;
        a1 += x[s0 * 64 + 32 + lane] * c0;
    }
    out[node * 64 + lane] = a0;
    out[node * 64 + 32 + lane] = a1;
}

// pull aggregation, 6 features: 8 threads per node (6 active)
__global__ void k_pull6(const float* __restrict__ x, const int* __restrict__ csrc,
                        const float* __restrict__ cnorm, const int* __restrict__ rowptr,
                        const float* __restrict__ dinv, float* __restrict__ out) {
    int gid = blockIdx.x * blockDim.x + threadIdx.x;
    int node = gid >> 3, f = gid & 7;
    if (node >= NN) return;
    int beg = rowptr[node], end = rowptr[node + 1];
    if (f >= 6) return;
    float dv = dinv[node];
    float a = x[node * 6 + f] * dv * dv;
    for (int j = beg; j < end; j++) {
        int s = csrc[j];
        a += x[s * 6 + f] * cnorm[j];
    }
    out[node * 6 + f] = a;
}

// out[row,:] = sigmoid(in[row,:] @ W[K,64] + b)   — in-place safe (rows staged in smem)
template <int K>
__global__ void k_xform(const float* __restrict__ in, const float* __restrict__ W,
                        const float* __restrict__ b, float* __restrict__ out) {
    __shared__ float sW[64 * 64];
    __shared__ float sx[8][64];
    int tid = threadIdx.x;  // 512
    for (int i = tid; i < K * 64; i += 512) sW[i] = W[i];
    int r = tid >> 6, o = tid & 63;
    int row = blockIdx.x * 8 + r;
    if (row < NN && o < K) sx[r][o] = in[row * K + o];
    __syncthreads();
    if (row < NN) {
        float acc = b[o];
#pragma unroll
        for (int k = 0; k < K; k++) acc += sx[r][k] * sW[k * 64 + o];
        out[row * 64 + o] = 1.0f / (1.0f + __expf(-acc));
    }
}

// head: out[row, 0..4] = in[row,:] @ Wl[64,5] + bl
__global__ void k_head(const float* __restrict__ in, const float* __restrict__ Wl,
                       const float* __restrict__ bl, float* __restrict__ out) {
    int idx = blockIdx.x * blockDim.x + threadIdx.x;
    int row = idx >> 3, o = idx & 7;
    if (row < NGNB && o < 5) {
        float acc = bl[o];
#pragma unroll
        for (int k = 0; k < 64; k++) acc += in[row * 64 + k] * Wl[k * 5 + o];
        out[row * 5 + o] = acc;
    }
}

extern "C" void kernel_launch(void* const* d_in, const int* in_sizes, int n_in,
                              void* d_out, int out_size) {
    const float* vf  = (const float*)d_in[0];
    const int*   edg = (const int*)d_in[1];
    const float* w   = (const float*)d_in[2];
    const float* W1  = (const float*)d_in[3];
    const float* b1  = (const float*)d_in[4];
    const float* W2  = (const float*)d_in[5];
    const float* b2  = (const float*)d_in[6];
    const float* W3  = (const float*)d_in[7];
    const float* b3  = (const float*)d_in[8];
    const float* W4  = (const float*)d_in[9];
    const float* b4  = (const float*)d_in[10];
    const float* Wl  = (const float*)d_in[11];
    const float* bl  = (const float*)d_in[12];
    float* out = (float*)d_out;

    const int* src = edg;
    const int* dst = edg + EE;

    float *bufA, *bufB, *dinv, *cnorm;
    int *cnt, *rowptr, *cursor, *csrc;
    cudaGetSymbolAddress((void**)&bufA, g_bufA);
    cudaGetSymbolAddress((void**)&bufB, g_bufB);
    cudaGetSymbolAddress((void**)&dinv, g_dinv);
    cudaGetSymbolAddress((void**)&cnt, g_cnt);
    cudaGetSymbolAddress((void**)&rowptr, g_rowptr);
    cudaGetSymbolAddress((void**)&cursor, g_cursor);
    cudaGetSymbolAddress((void**)&csrc, g_csrc);
    cudaGetSymbolAddress((void**)&cnorm, g_cnorm);

    const int T = 256;
    const int gN = (NN + T - 1) / T;
    const int gE = (EE + T - 1) / T;

    // --- CSR build + normalization (once per call) ---
    k_init<<<gN, T>>>(dinv, cnt);
    k_hist<<<gE, T>>>(dst, w, dinv, cnt);
    k_dinv<<<gN, T>>>(dinv);
    k_scan<<<1, SCAN_T>>>(cnt, rowptr, cursor);
    k_scatter<<<gE, T>>>(src, dst, w, dinv, cursor, csrc, cnorm);

    const int gP64 = (NN * 32 + T - 1) / T;  // warp per node
    const int gP6  = (NN * 8 + T - 1) / T;   // 8 threads per node
    const int gX   = (NN + 7) / 8;

    // Layer 1: pull(vf, F=6) -> bufA; xform K=6 -> bufB
    k_pull6<<<gP6, T>>>(vf, csrc, cnorm, rowptr, dinv, bufA);
    k_xform<6><<<gX, 512>>>(bufA, W1, b1, bufB);

    // Layer 2
    k_pull64<<<gP64, T>>>(bufB, csrc, cnorm, rowptr, dinv, bufA);
    k_xform<64><<<gX, 512>>>(bufA, W2, b2, bufA);

    // Layer 3
    k_pull64<<<gP64, T>>>(bufA, csrc, cnorm, rowptr, dinv, bufB);
    k_xform<64><<<gX, 512>>>(bufB, W3, b3, bufB);

    // Layer 4
    k_pull64<<<gP64, T>>>(bufB, csrc, cnorm, rowptr, dinv, bufA);
    k_xform<64><<<gX, 512>>>(bufA, W4, b4, bufA);

    // Head
    k_head<<<(NGNB * 8 + T - 1) / T, T>>>(bufA, Wl, bl, out);
}

// round 3
// speedup vs baseline: 2.2200x; 1.3023x over previous
#include <cuda_runtime.h>

#define NN 100000
#define EE 3200000
#define HH 64
#define NGNB 50000
#define SB 1024
#define NB ((NN + SB - 1) / SB)   // 98 scan blocks

// Static device scratch (no allocation in kernel_launch)
__device__ float g_bufA[NN * HH];
__device__ float g_bufB[NN * HH];
__device__ float g_dinv[NN];
__device__ int   g_cnt[NN];
__device__ int   g_rowptr[NN + 1];
__device__ int   g_cursor[NN];     // also used as incl-scan temp
__device__ int   g_csrc[EE];
__device__ float g_cnorm[EE];
__device__ int   g_bsum[NB];
__device__ int   g_boff[NB + 1];

// zero counters, init weighted degree with self-loop weight 1.0
__global__ void k_init(float* wdeg, int* cnt) {
    int i = blockIdx.x * blockDim.x + threadIdx.x;
    if (i < NN) { wdeg[i] = 1.0f; cnt[i] = 0; }
}

// histogram: weighted in-degree (for dinv) + edge counts (for CSR)
__global__ void k_hist(const int* __restrict__ dst, const float* __restrict__ w,
                       float* __restrict__ wdeg, int* __restrict__ cnt) {
    int e = blockIdx.x * blockDim.x + threadIdx.x;
    if (e < EE) {
        int d = dst[e];
        atomicAdd(&wdeg[d], w[e]);
        atomicAdd(&cnt[d], 1);
    }
}

__global__ void k_dinv(float* d) {
    int i = blockIdx.x * blockDim.x + threadIdx.x;
    if (i < NN) {
        float v = d[i];
        d[i] = (v > 0.0f) ? rsqrtf(v) : 0.0f;
    }
}

// --- multi-block scan: A) per-block inclusive scan, B) scan block sums, C) add offsets ---
__global__ void k_scanA(const int* __restrict__ cnt, int* __restrict__ incl,
                        int* __restrict__ bsum) {
    __shared__ int s[SB];
    int t = threadIdx.x;
    int idx = blockIdx.x * SB + t;
    int v = (idx < NN) ? cnt[idx] : 0;
    s[t] = v;
    __syncthreads();
#pragma unroll
    for (int off = 1; off < SB; off <<= 1) {
        int u = (t >= off) ? s[t - off] : 0;
        __syncthreads();
        s[t] += u;
        __syncthreads();
    }
    if (idx < NN) incl[idx] = s[t];
    if (t == SB - 1) bsum[blockIdx.x] = s[t];
}

__global__ void k_scanB(const int* __restrict__ bsum, int* __restrict__ boff) {
    __shared__ int s[128];
    int t = threadIdx.x;
    int v = (t < NB) ? bsum[t] : 0;
    s[t] = v;
    __syncthreads();
#pragma unroll
    for (int off = 1; off < 128; off <<= 1) {
        int u = (t >= off) ? s[t - off] : 0;
        __syncthreads();
        s[t] += u;
        __syncthreads();
    }
    if (t < NB) boff[t] = s[t] - v;        // exclusive
    if (t == NB - 1) boff[NB] = s[t];      // total
}

__global__ void k_scanC(const int* __restrict__ cnt, int* __restrict__ incl_cursor,
                        const int* __restrict__ boff, int* __restrict__ rowptr) {
    int t = threadIdx.x;
    int idx = blockIdx.x * SB + t;
    if (idx < NN) {
        int e = incl_cursor[idx] - cnt[idx] + boff[blockIdx.x];
        rowptr[idx] = e;
        incl_cursor[idx] = e;  // becomes the scatter cursor
    }
    if (idx == 0) rowptr[NN] = boff[NB];
}

// scatter edges into CSR (by dst), computing norm on the fly
__global__ void k_scatter(const int* __restrict__ src, const int* __restrict__ dst,
                          const float* __restrict__ w, const float* __restrict__ dinv,
                          int* __restrict__ cursor, int* __restrict__ csrc,
                          float* __restrict__ cnorm) {
    int e = blockIdx.x * blockDim.x + threadIdx.x;
    if (e < EE) {
        int s = src[e], d = dst[e];
        int pos = atomicAdd(&cursor[d], 1);
        csrc[pos] = s;
        cnorm[pos] = dinv[s] * w[e] * dinv[d];
    }
}

// pull aggregation, 64 features: one warp per node, atomic-free, 4-edge unroll
__global__ void k_pull64(const float* __restrict__ x, const int* __restrict__ csrc,
                         const float* __restrict__ cnorm, const int* __restrict__ rowptr,
                         const float* __restrict__ dinv, float* __restrict__ out) {
    int gid = blockIdx.x * blockDim.x + threadIdx.x;
    int node = gid >> 5, lane = gid & 31;
    if (node >= NN) return;
    float dv = dinv[node];
    float cs = dv * dv;  // self-loop norm
    float a0 = x[node * 64 + lane] * cs;
    float a1 = x[node * 64 + 32 + lane] * cs;
    int beg = rowptr[node], end = rowptr[node + 1];
    int j = beg;
    for (; j + 3 < end; j += 4) {
        int s0 = csrc[j], s1 = csrc[j + 1], s2 = csrc[j + 2], s3 = csrc[j + 3];
        float c0 = cnorm[j], c1 = cnorm[j + 1], c2 = cnorm[j + 2], c3 = cnorm[j + 3];
        float x00 = x[s0 * 64 + lane], x01 = x[s0 * 64 + 32 + lane];
        float x10 = x[s1 * 64 + lane], x11 = x[s1 * 64 + 32 + lane];
        float x20 = x[s2 * 64 + lane], x21 = x[s2 * 64 + 32 + lane];
        float x30 = x[s3 * 64 + lane], x31 = x[s3 * 64 + 32 + lane];
        a0 += x00 * c0; a1 += x01 * c0;
        a0 += x10 * c1; a1 += x11 * c1;
        a0 += x20 * c2; a1 += x21 * c2;
        a0 += x30 * c3; a1 += x31 * c3;
    }
    for (; j < end; j++) {
        int s0 = csrc[j];
        float c0 = cnorm[j];
        a0 += x[s0 * 64 + lane] * c0;
        a1 += x[s0 * 64 + 32 + lane] * c0;
    }
    out[node * 64 + lane] = a0;
    out[node * 64 + 32 + lane] = a1;
}

// pull aggregation, 6 features: 8 threads per node (6 active)
__global__ void k_pull6(const float* __restrict__ x, const int* __restrict__ csrc,
                        const float* __restrict__ cnorm, const int* __restrict__ rowptr,
                        const float* __restrict__ dinv, float* __restrict__ out) {
    int gid = blockIdx.x * blockDim.x + threadIdx.x;
    int node = gid >> 3, f = gid & 7;
    if (node >= NN) return;
    if (f >= 6) return;
    int beg = rowptr[node], end = rowptr[node + 1];
    float dv = dinv[node];
    float a = x[node * 6 + f] * dv * dv;
    for (int j = beg; j < end; j++) {
        int s = csrc[j];
        a += x[s * 6 + f] * cnorm[j];
    }
    out[node * 6 + f] = a;
}

// out[row,:] = sigmoid(in[row,:] @ W[K,64] + b) — 64 rows/block, in-place safe
template <int K>
__global__ void k_xform(const float* __restrict__ in, const float* __restrict__ W,
                        const float* __restrict__ b, float* __restrict__ out) {
    __shared__ float sW[K * 64];
    __shared__ float sx[64][K];
    int tid = threadIdx.x;  // 512
    for (int i = tid; i < K * 64; i += 512) sW[i] = W[i];
    int base = blockIdx.x * 64;
    for (int i = tid; i < 64 * K; i += 512) {
        int r = i / K, c = i % K;
        if (base + r < NN) sx[r][c] = in[(base + r) * K + c];
    }
    __syncthreads();
    int r0 = tid >> 6, o = tid & 63;
#pragma unroll
    for (int rr = 0; rr < 8; rr++) {
        int r = rr * 8 + r0;
        int row = base + r;
        if (row < NN) {
            float acc = b[o];
#pragma unroll
            for (int k = 0; k < K; k++) acc += sx[r][k] * sW[k * 64 + o];
            out[row * 64 + o] = 1.0f / (1.0f + __expf(-acc));
        }
    }
}

// head: out[row, 0..4] = in[row,:] @ Wl[64,5] + bl
__global__ void k_head(const float* __restrict__ in, const float* __restrict__ Wl,
                       const float* __restrict__ bl, float* __restrict__ out) {
    int idx = blockIdx.x * blockDim.x + threadIdx.x;
    int row = idx >> 3, o = idx & 7;
    if (row < NGNB && o < 5) {
        float acc = bl[o];
#pragma unroll
        for (int k = 0; k < 64; k++) acc += in[row * 64 + k] * Wl[k * 5 + o];
        out[row * 5 + o] = acc;
    }
}

extern "C" void kernel_launch(void* const* d_in, const int* in_sizes, int n_in,
                              void* d_out, int out_size) {
    const float* vf  = (const float*)d_in[0];
    const int*   edg = (const int*)d_in[1];
    const float* w   = (const float*)d_in[2];
    const float* W1  = (const float*)d_in[3];
    const float* b1  = (const float*)d_in[4];
    const float* W2  = (const float*)d_in[5];
    const float* b2  = (const float*)d_in[6];
    const float* W3  = (const float*)d_in[7];
    const float* b3  = (const float*)d_in[8];
    const float* W4  = (const float*)d_in[9];
    const float* b4  = (const float*)d_in[10];
    const float* Wl  = (const float*)d_in[11];
    const float* bl  = (const float*)d_in[12];
    float* out = (float*)d_out;

    const int* src = edg;
    const int* dst = edg + EE;

    float *bufA, *bufB, *dinv, *cnorm;
    int *cnt, *rowptr, *cursor, *csrc, *bsum, *boff;
    cudaGetSymbolAddress((void**)&bufA, g_bufA);
    cudaGetSymbolAddress((void**)&bufB, g_bufB);
    cudaGetSymbolAddress((void**)&dinv, g_dinv);
    cudaGetSymbolAddress((void**)&cnt, g_cnt);
    cudaGetSymbolAddress((void**)&rowptr, g_rowptr);
    cudaGetSymbolAddress((void**)&cursor, g_cursor);
    cudaGetSymbolAddress((void**)&csrc, g_csrc);
    cudaGetSymbolAddress((void**)&cnorm, g_cnorm);
    cudaGetSymbolAddress((void**)&bsum, g_bsum);
    cudaGetSymbolAddress((void**)&boff, g_boff);

    const int T = 256;
    const int gN = (NN + T - 1) / T;
    const int gE = (EE + T - 1) / T;

    // --- CSR build + normalization (once per call) ---
    k_init<<<gN, T>>>(dinv, cnt);
    k_hist<<<gE, T>>>(dst, w, dinv, cnt);
    k_dinv<<<gN, T>>>(dinv);
    k_scanA<<<NB, SB>>>(cnt, cursor, bsum);
    k_scanB<<<1, 128>>>(bsum, boff);
    k_scanC<<<NB, SB>>>(cnt, cursor, boff, rowptr);
    k_scatter<<<gE, T>>>(src, dst, w, dinv, cursor, csrc, cnorm);

    const int gP64 = (NN * 32 + T - 1) / T;  // warp per node
    const int gP6  = (NN * 8 + T - 1) / T;   // 8 threads per node
    const int gX   = (NN + 63) / 64;

    // Layer 1: pull(vf, F=6) -> bufA; xform K=6 -> bufB
    k_pull6<<<gP6, T>>>(vf, csrc, cnorm, rowptr, dinv, bufA);
    k_xform<6><<<gX, 512>>>(bufA, W1, b1, bufB);

    // Layer 2
    k_pull64<<<gP64, T>>>(bufB, csrc, cnorm, rowptr, dinv, bufA);
    k_xform<64><<<gX, 512>>>(bufA, W2, b2, bufA);

    // Layer 3
    k_pull64<<<gP64, T>>>(bufA, csrc, cnorm, rowptr, dinv, bufB);
    k_xform<64><<<gX, 512>>>(bufB, W3, b3, bufB);

    // Layer 4
    k_pull64<<<gP64, T>>>(bufB, csrc, cnorm, rowptr, dinv, bufA);
    k_xform<64><<<gX, 512>>>(bufA, W4, b4, bufA);

    // Head
    k_head<<<(NGNB * 8 + T - 1) / T, T>>>(bufA, Wl, bl, out);
}

// round 4
// speedup vs baseline: 2.3213x; 1.0457x over previous
#include <cuda_runtime.h>

#define NN 100000
#define EE 3200000
#define HH 64
#define NGNB 50000
#define SB 1024
#define NB ((NN + SB - 1) / SB)   // 98 scan blocks

// Static device scratch (no allocation in kernel_launch)
__device__ float4 g_bufA[NN * 16];   // float4-aligned node features
__device__ float4 g_bufB[NN * 16];
__device__ float  g_dinv[NN];
__device__ int    g_cnt[NN];
__device__ int    g_rowptr[NN + 1];
__device__ int    g_cursor[NN];      // also incl-scan temp
__device__ int2   g_ep[EE];          // packed (src, norm-bits)
__device__ int    g_bsum[NB];
__device__ int    g_boff[NB + 1];

__global__ void k_init(float* wdeg, int* cnt) {
    int i = blockIdx.x * blockDim.x + threadIdx.x;
    if (i < NN) { wdeg[i] = 1.0f; cnt[i] = 0; }
}

__global__ void k_hist(const int* __restrict__ dst, const float* __restrict__ w,
                       float* __restrict__ wdeg, int* __restrict__ cnt) {
    int e = blockIdx.x * blockDim.x + threadIdx.x;
    if (e < EE) {
        int d = dst[e];
        atomicAdd(&wdeg[d], w[e]);
        atomicAdd(&cnt[d], 1);
    }
}

__global__ void k_dinv(float* d) {
    int i = blockIdx.x * blockDim.x + threadIdx.x;
    if (i < NN) {
        float v = d[i];
        d[i] = (v > 0.0f) ? rsqrtf(v) : 0.0f;
    }
}

// --- multi-block scan ---
__global__ void k_scanA(const int* __restrict__ cnt, int* __restrict__ incl,
                        int* __restrict__ bsum) {
    __shared__ int s[SB];
    int t = threadIdx.x;
    int idx = blockIdx.x * SB + t;
    int v = (idx < NN) ? cnt[idx] : 0;
    s[t] = v;
    __syncthreads();
#pragma unroll
    for (int off = 1; off < SB; off <<= 1) {
        int u = (t >= off) ? s[t - off] : 0;
        __syncthreads();
        s[t] += u;
        __syncthreads();
    }
    if (idx < NN) incl[idx] = s[t];
    if (t == SB - 1) bsum[blockIdx.x] = s[t];
}

__global__ void k_scanB(const int* __restrict__ bsum, int* __restrict__ boff) {
    __shared__ int s[128];
    int t = threadIdx.x;
    int v = (t < NB) ? bsum[t] : 0;
    s[t] = v;
    __syncthreads();
#pragma unroll
    for (int off = 1; off < 128; off <<= 1) {
        int u = (t >= off) ? s[t - off] : 0;
        __syncthreads();
        s[t] += u;
        __syncthreads();
    }
    if (t < NB) boff[t] = s[t] - v;
    if (t == NB - 1) boff[NB] = s[t];
}

__global__ void k_scanC(const int* __restrict__ cnt, int* __restrict__ incl_cursor,
                        const int* __restrict__ boff, int* __restrict__ rowptr) {
    int t = threadIdx.x;
    int idx = blockIdx.x * SB + t;
    if (idx < NN) {
        int e = incl_cursor[idx] - cnt[idx] + boff[blockIdx.x];
        rowptr[idx] = e;
        incl_cursor[idx] = e;
    }
    if (idx == 0) rowptr[NN] = boff[NB];
}

// scatter edges into CSR (by dst), packed (src, norm)
__global__ void k_scatter(const int* __restrict__ src, const int* __restrict__ dst,
                          const float* __restrict__ w, const float* __restrict__ dinv,
                          int* __restrict__ cursor, int2* __restrict__ ep) {
    int e = blockIdx.x * blockDim.x + threadIdx.x;
    if (e < EE) {
        int s = src[e], d = dst[e];
        int pos = atomicAdd(&cursor[d], 1);
        float nrm = dinv[s] * w[e] * dinv[d];
        ep[pos] = make_int2(s, __float_as_int(nrm));
    }
}

// Fused: pull64 (float4 gather, 2 edges/warp-iter) + GEMM 64x64 + sigmoid
// LAST: additionally compute 5-wide head from smem, skip global y write.
// Block: 512 threads = 16 warps; processes 64 nodes in 4 chunks of 16.
template <bool LAST>
__global__ void __launch_bounds__(512)
k_pull_xform(const float4* __restrict__ x4, const int2* __restrict__ ep,
             const int* __restrict__ rowptr, const float* __restrict__ dinv,
             const float* __restrict__ W, const float* __restrict__ bias,
             const float* __restrict__ Wl, const float* __restrict__ bl,
             float* __restrict__ y, float* __restrict__ out) {
    __shared__ float sW[64 * 64];
    __shared__ float sx[16 * 68];
    __shared__ float sy[16 * 68];
    __shared__ float sWl[64 * 5];

    int tid = threadIdx.x;
    int w = tid >> 5, lane = tid & 31;
    int half = lane >> 4, fl = lane & 15;

#pragma unroll
    for (int i = tid; i < 64 * 64; i += 512) sW[i] = W[i];
    if (LAST) {
        for (int i = tid; i < 64 * 5; i += 512) sWl[i] = Wl[i];
    }
    __syncthreads();

    int base = blockIdx.x * 64;

#pragma unroll 1
    for (int ch = 0; ch < 4; ch++) {
        int node = base + ch * 16 + w;
        float4 acc = make_float4(0.f, 0.f, 0.f, 0.f);
        int beg = 0, end = 0;
        if (node < NN) {
            beg = rowptr[node];
            end = rowptr[node + 1];
            if (half == 0) {
                float dv = dinv[node];
                float cs = dv * dv;
                float4 v = x4[node * 16 + fl];
                acc.x = v.x * cs; acc.y = v.y * cs;
                acc.z = v.z * cs; acc.w = v.w * cs;
            }
        }
        // 2 edges per iteration: half-warp each
        for (int j = beg; j + 1 < end; j += 2) {
            int2 p = ep[j + half];
            float c = __int_as_float(p.y);
            float4 v = x4[p.x * 16 + fl];
            acc.x += v.x * c; acc.y += v.y * c;
            acc.z += v.z * c; acc.w += v.w * c;
        }
        if (((end - beg) & 1) && half == 0) {
            int2 p = ep[end - 1];
            float c = __int_as_float(p.y);
            float4 v = x4[p.x * 16 + fl];
            acc.x += v.x * c; acc.y += v.y * c;
            acc.z += v.z * c; acc.w += v.w * c;
        }
        // combine halves
        acc.x += __shfl_down_sync(0xffffffffu, acc.x, 16);
        acc.y += __shfl_down_sync(0xffffffffu, acc.y, 16);
        acc.z += __shfl_down_sync(0xffffffffu, acc.z, 16);
        acc.w += __shfl_down_sync(0xffffffffu, acc.w, 16);
        if (half == 0) *(float4*)&sx[w * 68 + fl * 4] = acc;
        __syncthreads();

        // GEMM: warp w -> row w; lane computes outputs (lane, lane+32)
        {
            float acc0 = bias[lane], acc1 = bias[lane + 32];
            const float* xr = &sx[w * 68];
#pragma unroll
            for (int k = 0; k < 64; k++) {
                float s = xr[k];
                acc0 += s * sW[k * 64 + lane];
                acc1 += s * sW[k * 64 + lane + 32];
            }
            float y0 = 1.0f / (1.0f + __expf(-acc0));
            float y1 = 1.0f / (1.0f + __expf(-acc1));
            if (!LAST) {
                if (node < NN) {
                    float* yr = (float*)&y[0];
                    yr[node * 64 + lane] = y0;
                    yr[node * 64 + lane + 32] = y1;
                }
            } else {
                sy[w * 68 + lane] = y0;
                sy[w * 68 + lane + 32] = y1;
            }
        }
        if (LAST) {
            __syncthreads();
            if (tid < 80) {
                int rr = tid / 5, oo = tid % 5;
                int nd = base + ch * 16 + rr;
                if (nd < NGNB) {
                    float a = bl[oo];
#pragma unroll
                    for (int k = 0; k < 64; k++) a += sy[rr * 68 + k] * sWl[k * 5 + oo];
                    out[nd * 5 + oo] = a;
                }
            }
        }
        __syncthreads();
    }
}

// pull aggregation, 6 features: 8 threads per node (6 active)
__global__ void k_pull6(const float* __restrict__ x, const int2* __restrict__ ep,
                        const int* __restrict__ rowptr, const float* __restrict__ dinv,
                        float* __restrict__ out) {
    int gid = blockIdx.x * blockDim.x + threadIdx.x;
    int node = gid >> 3, f = gid & 7;
    if (node >= NN) return;
    if (f >= 6) return;
    int beg = rowptr[node], end = rowptr[node + 1];
    float dv = dinv[node];
    float a = x[node * 6 + f] * dv * dv;
    for (int j = beg; j < end; j++) {
        int2 p = ep[j];
        a += x[p.x * 6 + f] * __int_as_float(p.y);
    }
    out[node * 6 + f] = a;
}

// out[row,:] = sigmoid(in[row,:] @ W[6,64] + b) — 64 rows/block
__global__ void k_xform6(const float* __restrict__ in, const float* __restrict__ W,
                         const float* __restrict__ b, float* __restrict__ out) {
    __shared__ float sW[6 * 64];
    __shared__ float sx[64][6];
    int tid = threadIdx.x;  // 512
    for (int i = tid; i < 6 * 64; i += 512) sW[i] = W[i];
    int base = blockIdx.x * 64;
    for (int i = tid; i < 64 * 6; i += 512) {
        int r = i / 6, c = i % 6;
        if (base + r < NN) sx[r][c] = in[(base + r) * 6 + c];
    }
    __syncthreads();
    int r0 = tid >> 6, o = tid & 63;
#pragma unroll
    for (int rr = 0; rr < 8; rr++) {
        int r = rr * 8 + r0;
        int row = base + r;
        if (row < NN) {
            float acc = b[o];
#pragma unroll
            for (int k = 0; k < 6; k++) acc += sx[r][k] * sW[k * 64 + o];
            out[row * 64 + o] = 1.0f / (1.0f + __expf(-acc));
        }
    }
}

extern "C" void kernel_launch(void* const* d_in, const int* in_sizes, int n_in,
                              void* d_out, int out_size) {
    const float* vf  = (const float*)d_in[0];
    const int*   edg = (const int*)d_in[1];
    const float* w   = (const float*)d_in[2];
    const float* W1  = (const float*)d_in[3];
    const float* b1  = (const float*)d_in[4];
    const float* W2  = (const float*)d_in[5];
    const float* b2  = (const float*)d_in[6];
    const float* W3  = (const float*)d_in[7];
    const float* b3  = (const float*)d_in[8];
    const float* W4  = (const float*)d_in[9];
    const float* b4  = (const float*)d_in[10];
    const float* Wl  = (const float*)d_in[11];
    const float* bl  = (const float*)d_in[12];
    float* out = (float*)d_out;

    const int* src = edg;
    const int* dst = edg + EE;

    float4 *bufA4, *bufB4;
    float *dinv;
    int *cnt, *rowptr, *cursor, *bsum, *boff;
    int2 *ep;
    cudaGetSymbolAddress((void**)&bufA4, g_bufA);
    cudaGetSymbolAddress((void**)&bufB4, g_bufB);
    cudaGetSymbolAddress((void**)&dinv, g_dinv);
    cudaGetSymbolAddress((void**)&cnt, g_cnt);
    cudaGetSymbolAddress((void**)&rowptr, g_rowptr);
    cudaGetSymbolAddress((void**)&cursor, g_cursor);
    cudaGetSymbolAddress((void**)&ep, g_ep);
    cudaGetSymbolAddress((void**)&bsum, g_bsum);
    cudaGetSymbolAddress((void**)&boff, g_boff);
    float* bufA = (float*)bufA4;
    float* bufB = (float*)bufB4;

    const int T = 256;
    const int gN = (NN + T - 1) / T;
    const int gE = (EE + T - 1) / T;

    // --- CSR build + normalization ---
    k_init<<<gN, T>>>(dinv, cnt);
    k_hist<<<gE, T>>>(dst, w, dinv, cnt);
    k_dinv<<<gN, T>>>(dinv);
    k_scanA<<<NB, SB>>>(cnt, cursor, bsum);
    k_scanB<<<1, 128>>>(bsum, boff);
    k_scanC<<<NB, SB>>>(cnt, cursor, boff, rowptr);
    k_scatter<<<gE, T>>>(src, dst, w, dinv, cursor, ep);

    const int gP6 = (NN * 8 + T - 1) / T;
    const int gX  = (NN + 63) / 64;
    const int gF  = (NN + 63) / 64;   // fused: 64 nodes/block

    // Layer 1: pull(vf, F=6) -> bufA(first 6 cols packed); xform K=6 -> bufB
    k_pull6<<<gP6, T>>>(vf, ep, rowptr, dinv, bufA);
    k_xform6<<<gX, 512>>>(bufA, W1, b1, bufB);

    // Layers 2-4 fused (pull + GEMM + sigmoid [+ head])
    k_pull_xform<false><<<gF, 512>>>(bufB4, ep, rowptr, dinv, W2, b2,
                                     nullptr, nullptr, bufA, nullptr);
    k_pull_xform<false><<<gF, 512>>>(bufA4, ep, rowptr, dinv, W3, b3,
                                     nullptr, nullptr, bufB, nullptr);
    k_pull_xform<true><<<gF, 512>>>(bufB4, ep, rowptr, dinv, W4, b4,
                                    Wl, bl, nullptr, out);
}

// round 5
// speedup vs baseline: 2.6016x; 1.1208x over previous
#include <cuda_runtime.h>

#define NN 100000
#define EE 3200000
#define HH 64
#define NGNB 50000
#define SB 1024
#define NB ((NN + SB - 1) / SB)   // 98 scan blocks

// Static device scratch (no allocation in kernel_launch)
__device__ float4 g_bufA[NN * 16];   // float4-aligned node features
__device__ float4 g_bufB[NN * 16];
__device__ float  g_dinv[NN];
__device__ int    g_cnt[NN];
__device__ int    g_rowptr[NN + 1];
__device__ int    g_cursor[NN];      // also incl-scan temp
__device__ int2   g_ep[EE];          // packed (src, norm-bits)
__device__ int    g_bsum[NB];
__device__ int    g_boff[NB + 1];

__global__ void k_init(float* wdeg, int* cnt) {
    int i = blockIdx.x * blockDim.x + threadIdx.x;
    if (i < NN) { wdeg[i] = 1.0f; cnt[i] = 0; }
}

__global__ void k_hist(const int* __restrict__ dst, const float* __restrict__ w,
                       float* __restrict__ wdeg, int* __restrict__ cnt) {
    int e = blockIdx.x * blockDim.x + threadIdx.x;
    if (e < EE) {
        int d = dst[e];
        atomicAdd(&wdeg[d], w[e]);
        atomicAdd(&cnt[d], 1);
    }
}

__global__ void k_dinv(float* d) {
    int i = blockIdx.x * blockDim.x + threadIdx.x;
    if (i < NN) {
        float v = d[i];
        d[i] = (v > 0.0f) ? rsqrtf(v) : 0.0f;
    }
}

// --- multi-block scan ---
__global__ void k_scanA(const int* __restrict__ cnt, int* __restrict__ incl,
                        int* __restrict__ bsum) {
    __shared__ int s[SB];
    int t = threadIdx.x;
    int idx = blockIdx.x * SB + t;
    int v = (idx < NN) ? cnt[idx] : 0;
    s[t] = v;
    __syncthreads();
#pragma unroll
    for (int off = 1; off < SB; off <<= 1) {
        int u = (t >= off) ? s[t - off] : 0;
        __syncthreads();
        s[t] += u;
        __syncthreads();
    }
    if (idx < NN) incl[idx] = s[t];
    if (t == SB - 1) bsum[blockIdx.x] = s[t];
}

__global__ void k_scanB(const int* __restrict__ bsum, int* __restrict__ boff) {
    __shared__ int s[128];
    int t = threadIdx.x;
    int v = (t < NB) ? bsum[t] : 0;
    s[t] = v;
    __syncthreads();
#pragma unroll
    for (int off = 1; off < 128; off <<= 1) {
        int u = (t >= off) ? s[t - off] : 0;
        __syncthreads();
        s[t] += u;
        __syncthreads();
    }
    if (t < NB) boff[t] = s[t] - v;
    if (t == NB - 1) boff[NB] = s[t];
}

__global__ void k_scanC(const int* __restrict__ cnt, int* __restrict__ incl_cursor,
                        const int* __restrict__ boff, int* __restrict__ rowptr) {
    int t = threadIdx.x;
    int idx = blockIdx.x * SB + t;
    if (idx < NN) {
        int e = incl_cursor[idx] - cnt[idx] + boff[blockIdx.x];
        rowptr[idx] = e;
        incl_cursor[idx] = e;
    }
    if (idx == 0) rowptr[NN] = boff[NB];
}

// scatter edges into CSR (by dst), packed (src, norm)
__global__ void k_scatter(const int* __restrict__ src, const int* __restrict__ dst,
                          const float* __restrict__ w, const float* __restrict__ dinv,
                          int* __restrict__ cursor, int2* __restrict__ ep) {
    int e = blockIdx.x * blockDim.x + threadIdx.x;
    if (e < EE) {
        int s = src[e], d = dst[e];
        int pos = atomicAdd(&cursor[d], 1);
        float nrm = dinv[s] * w[e] * dinv[d];
        ep[pos] = make_int2(s, __float_as_int(nrm));
    }
}

// gather one node's 64-feature aggregated row; result valid on lanes 0..15 as float4
__device__ __forceinline__ float4 gather_row(const float4* __restrict__ x4,
                                             const int2* __restrict__ ep,
                                             const int* __restrict__ rowptr,
                                             const float* __restrict__ dinv,
                                             int node, int half, int fl) {
    float4 acc = make_float4(0.f, 0.f, 0.f, 0.f);
    int beg = 0, end = 0;
    if (node < NN) {
        beg = rowptr[node];
        end = rowptr[node + 1];
        if (half == 0) {
            float dv = dinv[node];
            float cs = dv * dv;
            float4 v = x4[node * 16 + fl];
            acc.x = v.x * cs; acc.y = v.y * cs;
            acc.z = v.z * cs; acc.w = v.w * cs;
        }
    }
    for (int j = beg; j + 1 < end; j += 2) {
        int2 p = ep[j + half];
        float c = __int_as_float(p.y);
        float4 v = x4[p.x * 16 + fl];
        acc.x += v.x * c; acc.y += v.y * c;
        acc.z += v.z * c; acc.w += v.w * c;
    }
    if (((end - beg) & 1) && half == 0) {
        int2 p = ep[end - 1];
        float c = __int_as_float(p.y);
        float4 v = x4[p.x * 16 + fl];
        acc.x += v.x * c; acc.y += v.y * c;
        acc.z += v.z * c; acc.w += v.w * c;
    }
    // combine halves -> lanes 0..15
    acc.x += __shfl_down_sync(0xffffffffu, acc.x, 16);
    acc.y += __shfl_down_sync(0xffffffffu, acc.y, 16);
    acc.z += __shfl_down_sync(0xffffffffu, acc.z, 16);
    acc.w += __shfl_down_sync(0xffffffffu, acc.w, 16);
    return acc;
}

// Fused, warp-autonomous: pull + GEMM(64x64, paired nodes) + sigmoid [+ head].
// Block: 512 threads = 16 warps; each warp owns 8 nodes (4 pairs). One sync total.
template <bool LAST>
__global__ void __launch_bounds__(512)
k_pull_xform(const float4* __restrict__ x4, const int2* __restrict__ ep,
             const int* __restrict__ rowptr, const float* __restrict__ dinv,
             const float* __restrict__ W, const float* __restrict__ bias,
             const float* __restrict__ Wl, const float* __restrict__ bl,
             float* __restrict__ y, float* __restrict__ out) {
    __shared__ float sW[64 * 64];
    __shared__ float sWl[64 * 5];

    int tid = threadIdx.x;
    int w = tid >> 5, lane = tid & 31;
    int half = lane >> 4, fl = lane & 15;

#pragma unroll
    for (int i = tid; i < 64 * 64; i += 512) sW[i] = W[i];
    if (LAST) {
        for (int i = tid; i < 64 * 5; i += 512) sWl[i] = Wl[i];
    }
    float bias0 = bias[lane], bias1 = bias[lane + 32];
    __syncthreads();  // the only block sync

    int nbase = blockIdx.x * 128 + w * 8;

#pragma unroll 1
    for (int pr = 0; pr < 4; pr++) {
        int na = nbase + pr * 2;
        int nb = na + 1;

        float4 ra = gather_row(x4, ep, rowptr, dinv, na, half, fl);
        float4 rb = gather_row(x4, ep, rowptr, dinv, nb, half, fl);

        // paired GEMM: broadcast x values from lanes 0..15, share sW loads
        float a0 = bias0, a1 = bias1, b0 = bias0, b1 = bias1;
#pragma unroll
        for (int kk = 0; kk < 16; kk++) {
            float sax = __shfl_sync(0xffffffffu, ra.x, kk);
            float say = __shfl_sync(0xffffffffu, ra.y, kk);
            float saz = __shfl_sync(0xffffffffu, ra.z, kk);
            float saw = __shfl_sync(0xffffffffu, ra.w, kk);
            float sbx = __shfl_sync(0xffffffffu, rb.x, kk);
            float sby = __shfl_sync(0xffffffffu, rb.y, kk);
            float sbz = __shfl_sync(0xffffffffu, rb.z, kk);
            float sbw = __shfl_sync(0xffffffffu, rb.w, kk);
            const float* wp = &sW[kk * 4 * 64];
            float w00 = wp[lane],            w01 = wp[lane + 32];
            float w10 = wp[64 + lane],       w11 = wp[64 + lane + 32];
            float w20 = wp[128 + lane],      w21 = wp[128 + lane + 32];
            float w30 = wp[192 + lane],      w31 = wp[192 + lane + 32];
            a0 += sax * w00; a1 += sax * w01; b0 += sbx * w00; b1 += sbx * w01;
            a0 += say * w10; a1 += say * w11; b0 += sby * w10; b1 += sby * w11;
            a0 += saz * w20; a1 += saz * w21; b0 += sbz * w20; b1 += sbz * w21;
            a0 += saw * w30; a1 += saw * w31; b0 += sbw * w30; b1 += sbw * w31;
        }
        float ya0 = 1.0f / (1.0f + __expf(-a0));
        float ya1 = 1.0f / (1.0f + __expf(-a1));
        float yb0 = 1.0f / (1.0f + __expf(-b0));
        float yb1 = 1.0f / (1.0f + __expf(-b1));

        if (!LAST) {
            if (na < NN) { y[na * 64 + lane] = ya0; y[na * 64 + 32 + lane] = ya1; }
            if (nb < NN) { y[nb * 64 + lane] = yb0; y[nb * 64 + 32 + lane] = yb1; }
        } else {
            // head per node via warp shfl-reduce; y stays in registers
            if (na < NGNB) {
                float p[5];
#pragma unroll
                for (int o = 0; o < 5; o++)
                    p[o] = ya0 * sWl[lane * 5 + o] + ya1 * sWl[(lane + 32) * 5 + o];
#pragma unroll
                for (int o = 0; o < 5; o++)
#pragma unroll
                    for (int off = 16; off; off >>= 1)
                        p[o] += __shfl_down_sync(0xffffffffu, p[o], off);
                if (lane == 0) {
#pragma unroll
                    for (int o = 0; o < 5; o++) out[na * 5 + o] = p[o] + bl[o];
                }
            }
            if (nb < NGNB) {
                float p[5];
#pragma unroll
                for (int o = 0; o < 5; o++)
                    p[o] = yb0 * sWl[lane * 5 + o] + yb1 * sWl[(lane + 32) * 5 + o];
#pragma unroll
                for (int o = 0; o < 5; o++)
#pragma unroll
                    for (int off = 16; off; off >>= 1)
                        p[o] += __shfl_down_sync(0xffffffffu, p[o], off);
                if (lane == 0) {
#pragma unroll
                    for (int o = 0; o < 5; o++) out[nb * 5 + o] = p[o] + bl[o];
                }
            }
        }
    }
}

// pull aggregation, 6 features: 8 threads per node (6 active)
__global__ void k_pull6(const float* __restrict__ x, const int2* __restrict__ ep,
                        const int* __restrict__ rowptr, const float* __restrict__ dinv,
                        float* __restrict__ out) {
    int gid = blockIdx.x * blockDim.x + threadIdx.x;
    int node = gid >> 3, f = gid & 7;
    if (node >= NN) return;
    if (f >= 6) return;
    int beg = rowptr[node], end = rowptr[node + 1];
    float dv = dinv[node];
    float a = x[node * 6 + f] * dv * dv;
    for (int j = beg; j < end; j++) {
        int2 p = ep[j];
        a += x[p.x * 6 + f] * __int_as_float(p.y);
    }
    out[node * 6 + f] = a;
}

// out[row,:] = sigmoid(in[row,:] @ W[6,64] + b) — 64 rows/block
__global__ void k_xform6(const float* __restrict__ in, const float* __restrict__ W,
                         const float* __restrict__ b, float* __restrict__ out) {
    __shared__ float sW[6 * 64];
    __shared__ float sx[64][6];
    int tid = threadIdx.x;  // 512
    for (int i = tid; i < 6 * 64; i += 512) sW[i] = W[i];
    int base = blockIdx.x * 64;
    for (int i = tid; i < 64 * 6; i += 512) {
        int r = i / 6, c = i % 6;
        if (base + r < NN) sx[r][c] = in[(base + r) * 6 + c];
    }
    __syncthreads();
    int r0 = tid >> 6, o = tid & 63;
#pragma unroll
    for (int rr = 0; rr < 8; rr++) {
        int r = rr * 8 + r0;
        int row = base + r;
        if (row < NN) {
            float acc = b[o];
#pragma unroll
            for (int k = 0; k < 6; k++) acc += sx[r][k] * sW[k * 64 + o];
            out[row * 64 + o] = 1.0f / (1.0f + __expf(-acc));
        }
    }
}

extern "C" void kernel_launch(void* const* d_in, const int* in_sizes, int n_in,
                              void* d_out, int out_size) {
    const float* vf  = (const float*)d_in[0];
    const int*   edg = (const int*)d_in[1];
    const float* w   = (const float*)d_in[2];
    const float* W1  = (const float*)d_in[3];
    const float* b1  = (const float*)d_in[4];
    const float* W2  = (const float*)d_in[5];
    const float* b2  = (const float*)d_in[6];
    const float* W3  = (const float*)d_in[7];
    const float* b3  = (const float*)d_in[8];
    const float* W4  = (const float*)d_in[9];
    const float* b4  = (const float*)d_in[10];
    const float* Wl  = (const float*)d_in[11];
    const float* bl  = (const float*)d_in[12];
    float* out = (float*)d_out;

    const int* src = edg;
    const int* dst = edg + EE;

    float4 *bufA4, *bufB4;
    float *dinv;
    int *cnt, *rowptr, *cursor, *bsum, *boff;
    int2 *ep;
    cudaGetSymbolAddress((void**)&bufA4, g_bufA);
    cudaGetSymbolAddress((void**)&bufB4, g_bufB);
    cudaGetSymbolAddress((void**)&dinv, g_dinv);
    cudaGetSymbolAddress((void**)&cnt, g_cnt);
    cudaGetSymbolAddress((void**)&rowptr, g_rowptr);
    cudaGetSymbolAddress((void**)&cursor, g_cursor);
    cudaGetSymbolAddress((void**)&ep, g_ep);
    cudaGetSymbolAddress((void**)&bsum, g_bsum);
    cudaGetSymbolAddress((void**)&boff, g_boff);
    float* bufA = (float*)bufA4;
    float* bufB = (float*)bufB4;

    const int T = 256;
    const int gN = (NN + T - 1) / T;
    const int gE = (EE + T - 1) / T;

    // --- CSR build + normalization ---
    k_init<<<gN, T>>>(dinv, cnt);
    k_hist<<<gE, T>>>(dst, w, dinv, cnt);
    k_dinv<<<gN, T>>>(dinv);
    k_scanA<<<NB, SB>>>(cnt, cursor, bsum);
    k_scanB<<<1, 128>>>(bsum, boff);
    k_scanC<<<NB, SB>>>(cnt, cursor, boff, rowptr);
    k_scatter<<<gE, T>>>(src, dst, w, dinv, cursor, ep);

    const int gP6 = (NN * 8 + T - 1) / T;
    const int gX  = (NN + 63) / 64;
    const int gF  = (NN + 127) / 128;   // fused: 128 nodes/block

    // Layer 1: pull(vf, F=6) -> bufA; xform K=6 -> bufB
    k_pull6<<<gP6, T>>>(vf, ep, rowptr, dinv, bufA);
    k_xform6<<<gX, 512>>>(bufA, W1, b1, bufB);

    // Layers 2-4 fused (pull + GEMM + sigmoid [+ head])
    k_pull_xform<false><<<gF, 512>>>(bufB4, ep, rowptr, dinv, W2, b2,
                                     nullptr, nullptr, bufA, nullptr);
    k_pull_xform<false><<<gF, 512>>>(bufA4, ep, rowptr, dinv, W3, b3,
                                     nullptr, nullptr, bufB, nullptr);
    k_pull_xform<true><<<gF, 512>>>(bufB4, ep, rowptr, dinv, W4, b4,
                                    Wl, bl, nullptr, out);
}

// round 6
// speedup vs baseline: 3.0533x; 1.1736x over previous
#include <cuda_runtime.h>
#include <cuda_fp16.h>

#define NN 100000
#define EE 3200000
#define HH 64
#define NGNB 50000
#define SB 1024
#define NB ((NN + SB - 1) / SB)   // 98 scan blocks

// Static device scratch. Feature buffers hold 64 halves (128 B) per node.
__device__ uint4  g_bufA[NN * 8];
__device__ uint4  g_bufB[NN * 8];
__device__ float  g_dinv[NN];
__device__ int    g_cnt[NN];
__device__ int    g_rowptr[NN + 1];
__device__ int    g_cursor[NN];
__device__ int2   g_ep[EE];          // packed (src, norm-bits)
__device__ int    g_bsum[NB];
__device__ int    g_boff[NB + 1];

__global__ void k_init(float* wdeg, int* cnt) {
    int i = blockIdx.x * blockDim.x + threadIdx.x;
    if (i < NN) { wdeg[i] = 1.0f; cnt[i] = 0; }
}

__global__ void k_hist(const int* __restrict__ dst, const float* __restrict__ w,
                       float* __restrict__ wdeg, int* __restrict__ cnt) {
    int e = blockIdx.x * blockDim.x + threadIdx.x;
    if (e < EE) {
        int d = dst[e];
        atomicAdd(&wdeg[d], w[e]);
        atomicAdd(&cnt[d], 1);
    }
}

__global__ void k_dinv(float* d) {
    int i = blockIdx.x * blockDim.x + threadIdx.x;
    if (i < NN) {
        float v = d[i];
        d[i] = (v > 0.0f) ? rsqrtf(v) : 0.0f;
    }
}

// --- multi-block scan ---
__global__ void k_scanA(const int* __restrict__ cnt, int* __restrict__ incl,
                        int* __restrict__ bsum) {
    __shared__ int s[SB];
    int t = threadIdx.x;
    int idx = blockIdx.x * SB + t;
    int v = (idx < NN) ? cnt[idx] : 0;
    s[t] = v;
    __syncthreads();
#pragma unroll
    for (int off = 1; off < SB; off <<= 1) {
        int u = (t >= off) ? s[t - off] : 0;
        __syncthreads();
        s[t] += u;
        __syncthreads();
    }
    if (idx < NN) incl[idx] = s[t];
    if (t == SB - 1) bsum[blockIdx.x] = s[t];
}

__global__ void k_scanB(const int* __restrict__ bsum, int* __restrict__ boff) {
    __shared__ int s[128];
    int t = threadIdx.x;
    int v = (t < NB) ? bsum[t] : 0;
    s[t] = v;
    __syncthreads();
#pragma unroll
    for (int off = 1; off < 128; off <<= 1) {
        int u = (t >= off) ? s[t - off] : 0;
        __syncthreads();
        s[t] += u;
        __syncthreads();
    }
    if (t < NB) boff[t] = s[t] - v;
    if (t == NB - 1) boff[NB] = s[t];
}

__global__ void k_scanC(const int* __restrict__ cnt, int* __restrict__ incl_cursor,
                        const int* __restrict__ boff, int* __restrict__ rowptr) {
    int t = threadIdx.x;
    int idx = blockIdx.x * SB + t;
    if (idx < NN) {
        int e = incl_cursor[idx] - cnt[idx] + boff[blockIdx.x];
        rowptr[idx] = e;
        incl_cursor[idx] = e;
    }
    if (idx == 0) rowptr[NN] = boff[NB];
}

__global__ void k_scatter(const int* __restrict__ src, const int* __restrict__ dst,
                          const float* __restrict__ w, const float* __restrict__ dinv,
                          int* __restrict__ cursor, int2* __restrict__ ep) {
    int e = blockIdx.x * blockDim.x + threadIdx.x;
    if (e < EE) {
        int s = src[e], d = dst[e];
        int pos = atomicAdd(&cursor[d], 1);
        float nrm = dinv[s] * w[e] * dinv[d];
        ep[pos] = make_int2(s, __float_as_int(nrm));
    }
}

__device__ __forceinline__ void addh8(float a[8], uint4 v, float c) {
    const __half2* h = (const __half2*)&v;
#pragma unroll
    for (int i = 0; i < 4; i++) {
        float2 f = __half22float2(h[i]);
        a[2 * i]     += f.x * c;
        a[2 * i + 1] += f.y * c;
    }
}

// gather one node's aggregated row (64 halves -> fp32). 8 lanes/edge, 4 edges/iter.
// Result valid on lanes 0..7: lane fl holds features fl*8 .. fl*8+7 in acc[0..7].
__device__ __forceinline__ void gather_row_h(const uint4* __restrict__ x8,
                                             const int2* __restrict__ ep,
                                             const int* __restrict__ rowptr,
                                             const float* __restrict__ dinv,
                                             int node, int q, int fl, float acc[8]) {
#pragma unroll
    for (int i = 0; i < 8; i++) acc[i] = 0.f;
    int beg = 0, end = 0;
    if (node < NN) {
        beg = rowptr[node];
        end = rowptr[node + 1];
        if (q == 0) {
            float dv = dinv[node];
            addh8(acc, x8[node * 8 + fl], dv * dv);
        }
    }
    int cnt = end - beg;
    int nfull = cnt & ~3;
    for (int j = beg; j < beg + nfull; j += 4) {
        int2 p = ep[j + q];
        addh8(acc, x8[p.x * 8 + fl], __int_as_float(p.y));
    }
    if (q < (cnt & 3)) {
        int2 p = ep[beg + nfull + q];
        addh8(acc, x8[p.x * 8 + fl], __int_as_float(p.y));
    }
#pragma unroll
    for (int i = 0; i < 8; i++) {
        acc[i] += __shfl_down_sync(0xffffffffu, acc[i], 16);
        acc[i] += __shfl_down_sync(0xffffffffu, acc[i], 8);
    }
}

// Fused, warp-autonomous: half-gather + GEMM(64x64, paired) + sigmoid [+ head].
// Block: 512 threads = 16 warps; each warp owns 8 nodes (4 pairs). One block sync.
template <bool LAST>
__global__ void __launch_bounds__(512)
k_pull_xform(const uint4* __restrict__ x8, const int2* __restrict__ ep,
             const int* __restrict__ rowptr, const float* __restrict__ dinv,
             const float* __restrict__ W, const float* __restrict__ bias,
             const float* __restrict__ Wl, const float* __restrict__ bl,
             __half* __restrict__ y, float* __restrict__ out) {
    __shared__ float sW[64 * 64];
    __shared__ float sWl[64 * 5];

    int tid = threadIdx.x;
    int w = tid >> 5, lane = tid & 31;
    int q = lane >> 3, fl = lane & 7;

#pragma unroll
    for (int i = tid; i < 64 * 64; i += 512) sW[i] = W[i];
    if (LAST) {
        for (int i = tid; i < 64 * 5; i += 512) sWl[i] = Wl[i];
    }
    float bias0 = bias[lane], bias1 = bias[lane + 32];
    __syncthreads();  // the only block sync

    int nbase = blockIdx.x * 128 + w * 8;

#pragma unroll 1
    for (int pr = 0; pr < 4; pr++) {
        int na = nbase + pr * 2;
        int nb = na + 1;

        float ra[8], rb[8];
        gather_row_h(x8, ep, rowptr, dinv, na, q, fl, ra);
        gather_row_h(x8, ep, rowptr, dinv, nb, q, fl, rb);

        // paired GEMM: broadcast x from lanes 0..7, share sW loads
        float a0 = bias0, a1 = bias1, b0 = bias0, b1 = bias1;
#pragma unroll
        for (int kk = 0; kk < 8; kk++) {
#pragma unroll
            for (int i = 0; i < 8; i++) {
                float sa = __shfl_sync(0xffffffffu, ra[i], kk);
                float sb = __shfl_sync(0xffffffffu, rb[i], kk);
                int k = kk * 8 + i;
                float w0 = sW[k * 64 + lane], w1 = sW[k * 64 + lane + 32];
                a0 += sa * w0; a1 += sa * w1;
                b0 += sb * w0; b1 += sb * w1;
            }
        }
        float ya0 = 1.0f / (1.0f + __expf(-a0));
        float ya1 = 1.0f / (1.0f + __expf(-a1));
        float yb0 = 1.0f / (1.0f + __expf(-b0));
        float yb1 = 1.0f / (1.0f + __expf(-b1));

        if (!LAST) {
            if (na < NN) {
                y[na * 64 + lane] = __float2half_rn(ya0);
                y[na * 64 + lane + 32] = __float2half_rn(ya1);
            }
            if (nb < NN) {
                y[nb * 64 + lane] = __float2half_rn(yb0);
                y[nb * 64 + lane + 32] = __float2half_rn(yb1);
            }
        } else {
            if (na < NGNB) {
                float p[5];
#pragma unroll
                for (int o = 0; o < 5; o++)
                    p[o] = ya0 * sWl[lane * 5 + o] + ya1 * sWl[(lane + 32) * 5 + o];
#pragma unroll
                for (int o = 0; o < 5; o++)
#pragma unroll
                    for (int off = 16; off; off >>= 1)
                        p[o] += __shfl_down_sync(0xffffffffu, p[o], off);
                if (lane == 0) {
#pragma unroll
                    for (int o = 0; o < 5; o++) out[na * 5 + o] = p[o] + bl[o];
                }
            }
            if (nb < NGNB) {
                float p[5];
#pragma unroll
                for (int o = 0; o < 5; o++)
                    p[o] = yb0 * sWl[lane * 5 + o] + yb1 * sWl[(lane + 32) * 5 + o];
#pragma unroll
                for (int o = 0; o < 5; o++)
#pragma unroll
                    for (int off = 16; off; off >>= 1)
                        p[o] += __shfl_down_sync(0xffffffffu, p[o], off);
                if (lane == 0) {
#pragma unroll
                    for (int o = 0; o < 5; o++) out[nb * 5 + o] = p[o] + bl[o];
                }
            }
        }
    }
}

// pull aggregation, 6 features (fp32 in/out): 8 threads per node (6 active)
__global__ void k_pull6(const float* __restrict__ x, const int2* __restrict__ ep,
                        const int* __restrict__ rowptr, const float* __restrict__ dinv,
                        float* __restrict__ out) {
    int gid = blockIdx.x * blockDim.x + threadIdx.x;
    int node = gid >> 3, f = gid & 7;
    if (node >= NN) return;
    if (f >= 6) return;
    int beg = rowptr[node], end = rowptr[node + 1];
    float dv = dinv[node];
    float a = x[node * 6 + f] * dv * dv;
    for (int j = beg; j < end; j++) {
        int2 p = ep[j];
        a += x[p.x * 6 + f] * __int_as_float(p.y);
    }
    out[node * 6 + f] = a;
}

// out[row,:] = half(sigmoid(in[row,:] @ W[6,64] + b)) — 64 rows/block
__global__ void k_xform6(const float* __restrict__ in, const float* __restrict__ W,
                         const float* __restrict__ b, __half* __restrict__ out) {
    __shared__ float sW[6 * 64];
    __shared__ float sx[64][6];
    int tid = threadIdx.x;  // 512
    for (int i = tid; i < 6 * 64; i += 512) sW[i] = W[i];
    int base = blockIdx.x * 64;
    for (int i = tid; i < 64 * 6; i += 512) {
        int r = i / 6, c = i % 6;
        if (base + r < NN) sx[r][c] = in[(base + r) * 6 + c];
    }
    __syncthreads();
    int r0 = tid >> 6, o = tid & 63;
#pragma unroll
    for (int rr = 0; rr < 8; rr++) {
        int r = rr * 8 + r0;
        int row = base + r;
        if (row < NN) {
            float acc = b[o];
#pragma unroll
            for (int k = 0; k < 6; k++) acc += sx[r][k] * sW[k * 64 + o];
            out[row * 64 + o] = __float2half_rn(1.0f / (1.0f + __expf(-acc)));
        }
    }
}

extern "C" void kernel_launch(void* const* d_in, const int* in_sizes, int n_in,
                              void* d_out, int out_size) {
    const float* vf  = (const float*)d_in[0];
    const int*   edg = (const int*)d_in[1];
    const float* w   = (const float*)d_in[2];
    const float* W1  = (const float*)d_in[3];
    const float* b1  = (const float*)d_in[4];
    const float* W2  = (const float*)d_in[5];
    const float* b2  = (const float*)d_in[6];
    const float* W3  = (const float*)d_in[7];
    const float* b3  = (const float*)d_in[8];
    const float* W4  = (const float*)d_in[9];
    const float* b4  = (const float*)d_in[10];
    const float* Wl  = (const float*)d_in[11];
    const float* bl  = (const float*)d_in[12];
    float* out = (float*)d_out;

    const int* src = edg;
    const int* dst = edg + EE;

    uint4 *bufA8, *bufB8;
    float *dinv;
    int *cnt, *rowptr, *cursor, *bsum, *boff;
    int2 *ep;
    cudaGetSymbolAddress((void**)&bufA8, g_bufA);
    cudaGetSymbolAddress((void**)&bufB8, g_bufB);
    cudaGetSymbolAddress((void**)&dinv, g_dinv);
    cudaGetSymbolAddress((void**)&cnt, g_cnt);
    cudaGetSymbolAddress((void**)&rowptr, g_rowptr);
    cudaGetSymbolAddress((void**)&cursor, g_cursor);
    cudaGetSymbolAddress((void**)&ep, g_ep);
    cudaGetSymbolAddress((void**)&bsum, g_bsum);
    cudaGetSymbolAddress((void**)&boff, g_boff);

    const int T = 256;
    const int gN = (NN + T - 1) / T;
    const int gE = (EE + T - 1) / T;

    // --- CSR build + normalization ---
    k_init<<<gN, T>>>(dinv, cnt);
    k_hist<<<gE, T>>>(dst, w, dinv, cnt);
    k_dinv<<<gN, T>>>(dinv);
    k_scanA<<<NB, SB>>>(cnt, cursor, bsum);
    k_scanB<<<1, 128>>>(bsum, boff);
    k_scanC<<<NB, SB>>>(cnt, cursor, boff, rowptr);
    k_scatter<<<gE, T>>>(src, dst, w, dinv, cursor, ep);

    const int gP6 = (NN * 8 + T - 1) / T;
    const int gX  = (NN + 63) / 64;
    const int gF  = (NN + 127) / 128;   // fused: 128 nodes/block

    // Layer 1: pull6 (fp32 temp in bufA) -> xform6 -> half features in bufB
    k_pull6<<<gP6, T>>>(vf, ep, rowptr, dinv, (float*)bufA8);
    k_xform6<<<gX, 512>>>((float*)bufA8, W1, b1, (__half*)bufB8);

    // Layers 2-4 fused (half gather + GEMM + sigmoid [+ fp32 head])
    k_pull_xform<false><<<gF, 512>>>(bufB8, ep, rowptr, dinv, W2, b2,
                                     nullptr, nullptr, (__half*)bufA8, nullptr);
    k_pull_xform<false><<<gF, 512>>>(bufA8, ep, rowptr, dinv, W3, b3,
                                     nullptr, nullptr, (__half*)bufB8, nullptr);
    k_pull_xform<true><<<gF, 512>>>(bufB8, ep, rowptr, dinv, W4, b4,
                                    Wl, bl, nullptr, out);
}

// round 7
// speedup vs baseline: 3.4228x; 1.1210x over previous
#include <cuda_runtime.h>
#include <cuda_fp16.h>

#define NN 100000
#define EE 3200000
#define HH 64
#define NGNB 50000
#define SB 1024
#define NB ((NN + SB - 1) / SB)   // 98 scan blocks

// Static device scratch. Feature buffers hold 64 halves (128 B) per node.
__device__ uint4  g_bufA[NN * 8];
__device__ uint4  g_bufB[NN * 8];
__device__ float  g_dinv[NN];
__device__ int    g_cnt[NN];
__device__ int    g_rowptr[NN + 1];
__device__ int    g_cursor[NN];
__device__ int2   g_ep[EE];          // packed (src, norm-bits)
__device__ int    g_bsum[NB];
__device__ int    g_boff[NB + 1];

__global__ void k_init(float* wdeg, int* cnt) {
    int i = blockIdx.x * blockDim.x + threadIdx.x;
    if (i < NN) { wdeg[i] = 1.0f; cnt[i] = 0; }
}

__global__ void k_hist(const int* __restrict__ dst, const float* __restrict__ w,
                       float* __restrict__ wdeg, int* __restrict__ cnt) {
    int e = blockIdx.x * blockDim.x + threadIdx.x;
    if (e < EE) {
        int d = dst[e];
        atomicAdd(&wdeg[d], w[e]);
        atomicAdd(&cnt[d], 1);
    }
}

__global__ void k_dinv(float* d) {
    int i = blockIdx.x * blockDim.x + threadIdx.x;
    if (i < NN) {
        float v = d[i];
        d[i] = (v > 0.0f) ? rsqrtf(v) : 0.0f;
    }
}

// --- multi-block scan ---
__global__ void k_scanA(const int* __restrict__ cnt, int* __restrict__ incl,
                        int* __restrict__ bsum) {
    __shared__ int s[SB];
    int t = threadIdx.x;
    int idx = blockIdx.x * SB + t;
    int v = (idx < NN) ? cnt[idx] : 0;
    s[t] = v;
    __syncthreads();
#pragma unroll
    for (int off = 1; off < SB; off <<= 1) {
        int u = (t >= off) ? s[t - off] : 0;
        __syncthreads();
        s[t] += u;
        __syncthreads();
    }
    if (idx < NN) incl[idx] = s[t];
    if (t == SB - 1) bsum[blockIdx.x] = s[t];
}

__global__ void k_scanB(const int* __restrict__ bsum, int* __restrict__ boff) {
    __shared__ int s[128];
    int t = threadIdx.x;
    int v = (t < NB) ? bsum[t] : 0;
    s[t] = v;
    __syncthreads();
#pragma unroll
    for (int off = 1; off < 128; off <<= 1) {
        int u = (t >= off) ? s[t - off] : 0;
        __syncthreads();
        s[t] += u;
        __syncthreads();
    }
    if (t < NB) boff[t] = s[t] - v;
    if (t == NB - 1) boff[NB] = s[t];
}

__global__ void k_scanC(const int* __restrict__ cnt, int* __restrict__ incl_cursor,
                        const int* __restrict__ boff, int* __restrict__ rowptr) {
    int t = threadIdx.x;
    int idx = blockIdx.x * SB + t;
    if (idx < NN) {
        int e = incl_cursor[idx] - cnt[idx] + boff[blockIdx.x];
        rowptr[idx] = e;
        incl_cursor[idx] = e;
    }
    if (idx == 0) rowptr[NN] = boff[NB];
}

__global__ void k_scatter(const int* __restrict__ src, const int* __restrict__ dst,
                          const float* __restrict__ w, const float* __restrict__ dinv,
                          int* __restrict__ cursor, int2* __restrict__ ep) {
    int e = blockIdx.x * blockDim.x + threadIdx.x;
    if (e < EE) {
        int s = src[e], d = dst[e];
        int pos = atomicAdd(&cursor[d], 1);
        float nrm = dinv[s] * w[e] * dinv[d];
        ep[pos] = make_int2(s, __float_as_int(nrm));
    }
}

__device__ __forceinline__ void addh8(float a[8], uint4 v, float c) {
    const __half2* h = (const __half2*)&v;
#pragma unroll
    for (int i = 0; i < 4; i++) {
        float2 f = __half22float2(h[i]);
        a[2 * i]     += f.x * c;
        a[2 * i + 1] += f.y * c;
    }
}

// Interleaved gather for a node pair: both rows' loads in flight together.
// 8 lanes per edge, 4 edges per node per iter. Results on lanes 0..7.
__device__ __forceinline__ void gather2(const uint4* __restrict__ x8,
                                        const int2* __restrict__ ep,
                                        const int* __restrict__ rowptr,
                                        const float* __restrict__ dinv,
                                        int na, int nb, int nlim,
                                        int q, int fl,
                                        float ra[8], float rb[8]) {
#pragma unroll
    for (int i = 0; i < 8; i++) { ra[i] = 0.f; rb[i] = 0.f; }
    int bega = 0, enda = 0, begb = 0, endb = 0;
    if (na < nlim) {
        bega = rowptr[na]; enda = rowptr[na + 1];
        if (q == 0) {
            float dv = dinv[na];
            addh8(ra, x8[na * 8 + fl], dv * dv);
        }
    }
    if (nb < nlim) {
        begb = rowptr[nb]; endb = rowptr[nb + 1];
        if (q == 0) {
            float dv = dinv[nb];
            addh8(rb, x8[nb * 8 + fl], dv * dv);
        }
    }
    int ca = (enda - bega) & ~3, cb = (endb - begb) & ~3;
    int nmin = min(ca, cb);
    int t = 0;
    for (; t < nmin; t += 4) {
        int2 pa = ep[bega + t + q];
        int2 pb = ep[begb + t + q];
        addh8(ra, x8[pa.x * 8 + fl], __int_as_float(pa.y));
        addh8(rb, x8[pb.x * 8 + fl], __int_as_float(pb.y));
    }
    for (int u = t; u < ca; u += 4) {
        int2 pa = ep[bega + u + q];
        addh8(ra, x8[pa.x * 8 + fl], __int_as_float(pa.y));
    }
    for (int u = t; u < cb; u += 4) {
        int2 pb = ep[begb + u + q];
        addh8(rb, x8[pb.x * 8 + fl], __int_as_float(pb.y));
    }
    if (q < ((enda - bega) & 3)) {
        int2 pa = ep[bega + ca + q];
        addh8(ra, x8[pa.x * 8 + fl], __int_as_float(pa.y));
    }
    if (q < ((endb - begb) & 3)) {
        int2 pb = ep[begb + cb + q];
        addh8(rb, x8[pb.x * 8 + fl], __int_as_float(pb.y));
    }
#pragma unroll
    for (int i = 0; i < 8; i++) {
        ra[i] += __shfl_down_sync(0xffffffffu, ra[i], 16);
        ra[i] += __shfl_down_sync(0xffffffffu, ra[i], 8);
        rb[i] += __shfl_down_sync(0xffffffffu, rb[i], 16);
        rb[i] += __shfl_down_sync(0xffffffffu, rb[i], 8);
    }
}

// Fused, warp-autonomous: half-gather + GEMM(64x64, paired) + sigmoid [+ head].
// Block: 512 threads = 16 warps; each warp owns 8 nodes (4 pairs). One block sync.
// LAST: grid covers only NGNB nodes; head computed per-warp; y not written.
template <bool LAST>
__global__ void __launch_bounds__(512)
k_pull_xform(const uint4* __restrict__ x8, const int2* __restrict__ ep,
             const int* __restrict__ rowptr, const float* __restrict__ dinv,
             const float* __restrict__ W, const float* __restrict__ bias,
             const float* __restrict__ Wl, const float* __restrict__ bl,
             __half* __restrict__ y, float* __restrict__ out) {
    __shared__ float sW[64 * 64];
    __shared__ float sWl[64 * 5];

    const int nlim = LAST ? NGNB : NN;

    int tid = threadIdx.x;
    int w = tid >> 5, lane = tid & 31;
    int q = lane >> 3, fl = lane & 7;

#pragma unroll
    for (int i = tid; i < 64 * 64; i += 512) sW[i] = W[i];
    if (LAST) {
        for (int i = tid; i < 64 * 5; i += 512) sWl[i] = Wl[i];
    }
    float bias0 = bias[lane], bias1 = bias[lane + 32];
    __syncthreads();  // the only block sync

    int nbase = blockIdx.x * 128 + w * 8;

#pragma unroll 1
    for (int pr = 0; pr < 4; pr++) {
        int na = nbase + pr * 2;
        int nb = na + 1;

        float ra[8], rb[8];
        gather2(x8, ep, rowptr, dinv, na, nb, nlim, q, fl, ra, rb);

        // paired GEMM: broadcast x from lanes 0..7, share sW loads
        float a0 = bias0, a1 = bias1, b0 = bias0, b1 = bias1;
#pragma unroll
        for (int kk = 0; kk < 8; kk++) {
#pragma unroll
            for (int i = 0; i < 8; i++) {
                float sa = __shfl_sync(0xffffffffu, ra[i], kk);
                float sb = __shfl_sync(0xffffffffu, rb[i], kk);
                int k = kk * 8 + i;
                float w0 = sW[k * 64 + lane], w1 = sW[k * 64 + lane + 32];
                a0 += sa * w0; a1 += sa * w1;
                b0 += sb * w0; b1 += sb * w1;
            }
        }
        float ya0 = 1.0f / (1.0f + __expf(-a0));
        float ya1 = 1.0f / (1.0f + __expf(-a1));
        float yb0 = 1.0f / (1.0f + __expf(-b0));
        float yb1 = 1.0f / (1.0f + __expf(-b1));

        if (!LAST) {
            if (na < NN) {
                y[na * 64 + lane] = __float2half_rn(ya0);
                y[na * 64 + lane + 32] = __float2half_rn(ya1);
            }
            if (nb < NN) {
                y[nb * 64 + lane] = __float2half_rn(yb0);
                y[nb * 64 + lane + 32] = __float2half_rn(yb1);
            }
        } else {
            if (na < NGNB) {
                float p[5];
#pragma unroll
                for (int o = 0; o < 5; o++)
                    p[o] = ya0 * sWl[lane * 5 + o] + ya1 * sWl[(lane + 32) * 5 + o];
#pragma unroll
                for (int o = 0; o < 5; o++)
#pragma unroll
                    for (int off = 16; off; off >>= 1)
                        p[o] += __shfl_down_sync(0xffffffffu, p[o], off);
                if (lane == 0) {
#pragma unroll
                    for (int o = 0; o < 5; o++) out[na * 5 + o] = p[o] + bl[o];
                }
            }
            if (nb < NGNB) {
                float p[5];
#pragma unroll
                for (int o = 0; o < 5; o++)
                    p[o] = yb0 * sWl[lane * 5 + o] + yb1 * sWl[(lane + 32) * 5 + o];
#pragma unroll
                for (int o = 0; o < 5; o++)
#pragma unroll
                    for (int off = 16; off; off >>= 1)
                        p[o] += __shfl_down_sync(0xffffffffu, p[o], off);
                if (lane == 0) {
#pragma unroll
                    for (int o = 0; o < 5; o++) out[nb * 5 + o] = p[o] + bl[o];
                }
            }
        }
    }
}

// pull aggregation, 6 features (fp32 in/out): 8 threads per node (6 active)
__global__ void k_pull6(const float* __restrict__ x, const int2* __restrict__ ep,
                        const int* __restrict__ rowptr, const float* __restrict__ dinv,
                        float* __restrict__ out) {
    int gid = blockIdx.x * blockDim.x + threadIdx.x;
    int node = gid >> 3, f = gid & 7;
    if (node >= NN) return;
    if (f >= 6) return;
    int beg = rowptr[node], end = rowptr[node + 1];
    float dv = dinv[node];
    float a = x[node * 6 + f] * dv * dv;
    for (int j = beg; j < end; j++) {
        int2 p = ep[j];
        a += x[p.x * 6 + f] * __int_as_float(p.y);
    }
    out[node * 6 + f] = a;
}

// out[row,:] = half(sigmoid(in[row,:] @ W[6,64] + b)) — 64 rows/block
__global__ void k_xform6(const float* __restrict__ in, const float* __restrict__ W,
                         const float* __restrict__ b, __half* __restrict__ out) {
    __shared__ float sW[6 * 64];
    __shared__ float sx[64][6];
    int tid = threadIdx.x;  // 512
    for (int i = tid; i < 6 * 64; i += 512) sW[i] = W[i];
    int base = blockIdx.x * 64;
    for (int i = tid; i < 64 * 6; i += 512) {
        int r = i / 6, c = i % 6;
        if (base + r < NN) sx[r][c] = in[(base + r) * 6 + c];
    }
    __syncthreads();
    int r0 = tid >> 6, o = tid & 63;
#pragma unroll
    for (int rr = 0; rr < 8; rr++) {
        int r = rr * 8 + r0;
        int row = base + r;
        if (row < NN) {
            float acc = b[o];
#pragma unroll
            for (int k = 0; k < 6; k++) acc += sx[r][k] * sW[k * 64 + o];
            out[row * 64 + o] = __float2half_rn(1.0f / (1.0f + __expf(-acc)));
        }
    }
}

extern "C" void kernel_launch(void* const* d_in, const int* in_sizes, int n_in,
                              void* d_out, int out_size) {
    const float* vf  = (const float*)d_in[0];
    const int*   edg = (const int*)d_in[1];
    const float* w   = (const float*)d_in[2];
    const float* W1  = (const float*)d_in[3];
    const float* b1  = (const float*)d_in[4];
    const float* W2  = (const float*)d_in[5];
    const float* b2  = (const float*)d_in[6];
    const float* W3  = (const float*)d_in[7];
    const float* b3  = (const float*)d_in[8];
    const float* W4  = (const float*)d_in[9];
    const float* b4  = (const float*)d_in[10];
    const float* Wl  = (const float*)d_in[11];
    const float* bl  = (const float*)d_in[12];
    float* out = (float*)d_out;

    const int* src = edg;
    const int* dst = edg + EE;

    uint4 *bufA8, *bufB8;
    float *dinv;
    int *cnt, *rowptr, *cursor, *bsum, *boff;
    int2 *ep;
    cudaGetSymbolAddress((void**)&bufA8, g_bufA);
    cudaGetSymbolAddress((void**)&bufB8, g_bufB);
    cudaGetSymbolAddress((void**)&dinv, g_dinv);
    cudaGetSymbolAddress((void**)&cnt, g_cnt);
    cudaGetSymbolAddress((void**)&rowptr, g_rowptr);
    cudaGetSymbolAddress((void**)&cursor, g_cursor);
    cudaGetSymbolAddress((void**)&ep, g_ep);
    cudaGetSymbolAddress((void**)&bsum, g_bsum);
    cudaGetSymbolAddress((void**)&boff, g_boff);

    const int T = 256;
    const int gN = (NN + T - 1) / T;
    const int gE = (EE + T - 1) / T;

    // --- CSR build + normalization ---
    k_init<<<gN, T>>>(dinv, cnt);
    k_hist<<<gE, T>>>(dst, w, dinv, cnt);
    k_dinv<<<gN, T>>>(dinv);
    k_scanA<<<NB, SB>>>(cnt, cursor, bsum);
    k_scanB<<<1, 128>>>(bsum, boff);
    k_scanC<<<NB, SB>>>(cnt, cursor, boff, rowptr);
    k_scatter<<<gE, T>>>(src, dst, w, dinv, cursor, ep);

    const int gP6 = (NN * 8 + T - 1) / T;
    const int gX  = (NN + 63) / 64;
    const int gF  = (NN + 127) / 128;      // fused: 128 nodes/block
    const int gFL = (NGNB + 127) / 128;    // last layer: only head rows

    // Layer 1: pull6 (fp32 temp in bufA) -> xform6 -> half features in bufB
    k_pull6<<<gP6, T>>>(vf, ep, rowptr, dinv, (float*)bufA8);
    k_xform6<<<gX, 512>>>((float*)bufA8, W1, b1, (__half*)bufB8);

    // Layers 2-4 fused (half gather + GEMM + sigmoid [+ fp32 head])
    k_pull_xform<false><<<gF, 512>>>(bufB8, ep, rowptr, dinv, W2, b2,
                                     nullptr, nullptr, (__half*)bufA8, nullptr);
    k_pull_xform<false><<<gF, 512>>>(bufA8, ep, rowptr, dinv, W3, b3,
                                     nullptr, nullptr, (__half*)bufB8, nullptr);
    k_pull_xform<true><<<gFL, 512>>>(bufB8, ep, rowptr, dinv, W4, b4,
                                     Wl, bl, nullptr, out);
}